// round 3
// baseline (speedup 1.0000x reference)
#include <cuda_runtime.h>
#include <math.h>

// Problem shape (fixed per reference)
#define NB     2
#define NSEQ   2048
#define DMODEL 1024
#define NINNER 1024
#define NH     16
#define NDH    64
#define MTOT   (NB * NSEQ)   // 4096

// Scratch (allocation-free rule: __device__ globals)
__device__ float g_Q [MTOT * NINNER];       // 16 MB
__device__ float g_KV[MTOT * 2 * NINNER];   // 32 MB
__device__ float g_A [MTOT * NINNER];       // 16 MB (attention output, pre-proj)

// ---------------------------------------------------------------------------
// fp32 tiled GEMM: C[M,N] = A[M,K] @ B[K,N] (+ bias). 64x64x16 tiles,
// 256 threads, 4x4 microtile per thread, float4 global loads.
// M,N,K all multiples of 64/16 here -> no bounds checks.
// ---------------------------------------------------------------------------
__global__ __launch_bounds__(256) void gemm_kernel(
    const float* __restrict__ A, const float* __restrict__ B,
    const float* __restrict__ bias, float* __restrict__ C,
    int M, int N, int K)
{
    __shared__ float sA[64 * 16];
    __shared__ float sB[16 * 64];

    const int tid = threadIdx.x;
    const int tx  = tid & 15;         // 0..15 (N direction)
    const int ty  = tid >> 4;         // 0..15 (M direction)
    const int bm  = blockIdx.y * 64;
    const int bn  = blockIdx.x * 64;

    // load assignments
    const int ar = tid >> 2;            // 0..63
    const int ac = (tid & 3) << 2;      // 0,4,8,12
    const int br = tid >> 4;            // 0..15
    const int bc = (tid & 15) << 2;     // 0..60

    const float* Aptr = A + (size_t)(bm + ar) * K + ac;
    const float* Bptr = B + (size_t)br * N + bn + bc;

    float acc[4][4] = {};

    for (int k0 = 0; k0 < K; k0 += 16) {
        float4 av = *(const float4*)(Aptr + k0);
        float4 bv = *(const float4*)(Bptr + (size_t)k0 * N);
        __syncthreads();
        *(float4*)&sA[ar * 16 + ac] = av;
        *(float4*)&sB[br * 64 + bc] = bv;
        __syncthreads();

        #pragma unroll
        for (int kk = 0; kk < 16; kk++) {
            float a[4], b[4];
            #pragma unroll
            for (int i = 0; i < 4; i++) a[i] = sA[(ty * 4 + i) * 16 + kk];
            #pragma unroll
            for (int j = 0; j < 4; j++) b[j] = sB[kk * 64 + tx * 4 + j];
            #pragma unroll
            for (int i = 0; i < 4; i++)
                #pragma unroll
                for (int j = 0; j < 4; j++)
                    acc[i][j] = fmaf(a[i], b[j], acc[i][j]);
        }
    }

    const int colb = bn + tx * 4;
    float b0 = 0.f, b1 = 0.f, b2 = 0.f, b3 = 0.f;
    if (bias) { b0 = bias[colb]; b1 = bias[colb + 1]; b2 = bias[colb + 2]; b3 = bias[colb + 3]; }
    #pragma unroll
    for (int i = 0; i < 4; i++) {
        const int row = bm + ty * 4 + i;
        float4 o;
        o.x = acc[i][0] + b0; o.y = acc[i][1] + b1;
        o.z = acc[i][2] + b2; o.w = acc[i][3] + b3;
        *(float4*)&C[(size_t)row * N + colb] = o;
    }
}

// ---------------------------------------------------------------------------
// fp32 flash attention. One CTA handles 64 query rows of one (batch, head).
// BM=BN=64, D=64. Online softmax, P buffer reuses the K smem region.
// smem: sQ[64*64] + sKP[64*65 padded] + sV[64*64] = 49408 B (dynamic).
// ---------------------------------------------------------------------------
#define FLASH_SMEM_FLOATS (64 * 64 + 64 * 65 + 64 * 64)
#define FLASH_SMEM_BYTES  (FLASH_SMEM_FLOATS * 4)

__global__ __launch_bounds__(256) void flash_kernel(
    const float* __restrict__ Q, const float* __restrict__ KV,
    float* __restrict__ O)
{
    extern __shared__ float sm[];
    float* sQ  = sm;                       // [64][64]
    float* sKP = sm + 64 * 64;             // [64][65] K tile, later P tile
    float* sV  = sm + 64 * 64 + 64 * 65;   // [64][64]

    const int tid = threadIdx.x;
    const int tx  = tid & 15;   // col group (key idx / head-dim in PV)
    const int ty  = tid >> 4;   // row group (query rows)
    const int m0  = blockIdx.x * 64;
    const int bh  = blockIdx.y;
    const int b   = bh >> 4;
    const int h   = bh & 15;

    const float* Qb = Q  + (size_t)b * NSEQ * NINNER     + (size_t)h * NDH;
    const float* Kb = KV + (size_t)b * NSEQ * 2 * NINNER + (size_t)h * NDH;
    const float* Vb = Kb + NINNER;
    float*       Ob = O  + (size_t)b * NSEQ * NINNER     + (size_t)h * NDH;

    // Load Q tile (64 rows x 64 cols), float4
    #pragma unroll
    for (int rep = 0; rep < 4; rep++) {
        const int lin = rep * 256 + tid;
        const int r   = lin >> 4;
        const int c   = (lin & 15) << 2;
        *(float4*)&sQ[r * 64 + c] =
            *(const float4*)&Qb[(size_t)(m0 + r) * NINNER + c];
    }

    float m[4], l[4], o[4][4];
    #pragma unroll
    for (int i = 0; i < 4; i++) {
        m[i] = -INFINITY; l[i] = 0.f;
        #pragma unroll
        for (int j = 0; j < 4; j++) o[i][j] = 0.f;
    }
    const float scale = 0.125f;   // 64^-0.5

    for (int j0 = 0; j0 < NSEQ; j0 += 64) {
        __syncthreads();   // previous iteration's P/V reads done
        // Load K tile (padded scalar stores) + V tile (float4)
        #pragma unroll
        for (int rep = 0; rep < 4; rep++) {
            const int lin = rep * 256 + tid;
            const int r   = lin >> 4;
            const int c   = (lin & 15) << 2;
            const size_t grow = (size_t)(j0 + r) * (2 * NINNER);
            float4 kv = *(const float4*)&Kb[grow + c];
            sKP[r * 65 + c + 0] = kv.x;
            sKP[r * 65 + c + 1] = kv.y;
            sKP[r * 65 + c + 2] = kv.z;
            sKP[r * 65 + c + 3] = kv.w;
            *(float4*)&sV[r * 64 + c] = *(const float4*)&Vb[grow + c];
        }
        __syncthreads();

        // S = Q @ K^T  (4x4 per thread)
        float S[4][4] = {};
        #pragma unroll 16
        for (int kk = 0; kk < 64; kk++) {
            float a[4], bb[4];
            #pragma unroll
            for (int i = 0; i < 4; i++) a[i]  = sQ [(ty * 4 + i) * 64 + kk];
            #pragma unroll
            for (int j = 0; j < 4; j++) bb[j] = sKP[(tx * 4 + j) * 65 + kk];
            #pragma unroll
            for (int i = 0; i < 4; i++)
                #pragma unroll
                for (int j = 0; j < 4; j++)
                    S[i][j] = fmaf(a[i], bb[j], S[i][j]);
        }

        // Online softmax update (row state replicated across the 16 tx threads)
        #pragma unroll
        for (int i = 0; i < 4; i++) {
            #pragma unroll
            for (int j = 0; j < 4; j++) S[i][j] *= scale;
            float mr = fmaxf(fmaxf(S[i][0], S[i][1]), fmaxf(S[i][2], S[i][3]));
            mr = fmaxf(mr, __shfl_xor_sync(0xffffffff, mr, 1));
            mr = fmaxf(mr, __shfl_xor_sync(0xffffffff, mr, 2));
            mr = fmaxf(mr, __shfl_xor_sync(0xffffffff, mr, 4));
            mr = fmaxf(mr, __shfl_xor_sync(0xffffffff, mr, 8));
            const float mn    = fmaxf(m[i], mr);
            const float alpha = __expf(m[i] - mn);
            float rs = 0.f;
            #pragma unroll
            for (int j = 0; j < 4; j++) { S[i][j] = __expf(S[i][j] - mn); rs += S[i][j]; }
            rs += __shfl_xor_sync(0xffffffff, rs, 1);
            rs += __shfl_xor_sync(0xffffffff, rs, 2);
            rs += __shfl_xor_sync(0xffffffff, rs, 4);
            rs += __shfl_xor_sync(0xffffffff, rs, 8);
            l[i] = l[i] * alpha + rs;
            m[i] = mn;
            #pragma unroll
            for (int j = 0; j < 4; j++) o[i][j] *= alpha;
        }

        __syncthreads();   // everyone done reading sKP as K
        // Write P into sKP
        #pragma unroll
        for (int i = 0; i < 4; i++)
            #pragma unroll
            for (int j = 0; j < 4; j++)
                sKP[(ty * 4 + i) * 65 + tx * 4 + j] = S[i][j];
        __syncthreads();

        // O += P @ V
        #pragma unroll 16
        for (int jj = 0; jj < 64; jj++) {
            float p[4], v[4];
            #pragma unroll
            for (int i = 0; i < 4; i++) p[i] = sKP[(ty * 4 + i) * 65 + jj];
            #pragma unroll
            for (int j = 0; j < 4; j++) v[j] = sV[jj * 64 + tx * 4 + j];
            #pragma unroll
            for (int i = 0; i < 4; i++)
                #pragma unroll
                for (int j = 0; j < 4; j++)
                    o[i][j] = fmaf(p[i], v[j], o[i][j]);
        }
    }

    // Epilogue: normalize + store
    #pragma unroll
    for (int i = 0; i < 4; i++) {
        const float inv = 1.0f / l[i];
        float4 out;
        out.x = o[i][0] * inv; out.y = o[i][1] * inv;
        out.z = o[i][2] * inv; out.w = o[i][3] * inv;
        *(float4*)&Ob[(size_t)(m0 + ty * 4 + i) * NINNER + tx * 4] = out;
    }
}

// ---------------------------------------------------------------------------
extern "C" void kernel_launch(void* const* d_in, const int* in_sizes, int n_in,
                              void* d_out, int out_size)
{
    const float* X   = (const float*)d_in[0];   // queries [2,2048,1024]
    const float* Wq  = (const float*)d_in[1];   // [1024,1024]
    const float* Wkv = (const float*)d_in[2];   // [1024,2048]
    const float* Wo  = (const float*)d_in[3];   // [1024,1024]
    const float* bo  = (const float*)d_in[4];   // [1024]
    float* out = (float*)d_out;                 // [2,2048,1024]

    float *Qb, *KVb, *Ab;
    cudaGetSymbolAddress((void**)&Qb,  g_Q);
    cudaGetSymbolAddress((void**)&KVb, g_KV);
    cudaGetSymbolAddress((void**)&Ab,  g_A);

    cudaFuncSetAttribute(flash_kernel,
                         cudaFuncAttributeMaxDynamicSharedMemorySize,
                         FLASH_SMEM_BYTES);

    dim3 blk(256);

    // Q = X @ Wq
    gemm_kernel<<<dim3(NINNER / 64, MTOT / 64), blk>>>(
        X, Wq, nullptr, Qb, MTOT, NINNER, DMODEL);
    // KV = X @ Wkv
    gemm_kernel<<<dim3(2 * NINNER / 64, MTOT / 64), blk>>>(
        X, Wkv, nullptr, KVb, MTOT, 2 * NINNER, DMODEL);
    // Flash attention
    flash_kernel<<<dim3(NSEQ / 64, NB * NH), blk, FLASH_SMEM_BYTES>>>(
        Qb, KVb, Ab);
    // out = A @ Wo + bo
    gemm_kernel<<<dim3(DMODEL / 64, MTOT / 64), blk>>>(
        Ab, Wo, bo, out, MTOT, DMODEL, NINNER);
}

// round 7
// speedup vs baseline: 4.3949x; 4.3949x over previous
#include <cuda_runtime.h>
#include <math.h>
#include <stdint.h>

// Problem shape (fixed per reference)
#define NB     2
#define NSEQ   2048
#define DMODEL 1024
#define NINNER 1024
#define NH     16
#define NDH    64
#define MTOT   (NB * NSEQ)   // 4096

// Scratch (allocation-free rule: __device__ globals)
__device__ float g_Q  [MTOT * NINNER];        // 16 MB
__device__ float g_KV [MTOT * 2 * NINNER];    // 32 MB
__device__ float g_A  [MTOT * NINNER];        // 16 MB
__device__ float g_WqT [NINNER * DMODEL];     // 4 MB   [N][K]
__device__ float g_WkvT[2 * NINNER * DMODEL]; // 8 MB   [N][K]
__device__ float g_WoT [DMODEL * NINNER];     // 4 MB   [N][K]

// ===========================================================================
// Helpers (baseline PTX only — no arch-'a' features; ptxas targets sm_103)
// ===========================================================================
__device__ __forceinline__ uint32_t f2tf32(float x) {
    uint32_t u;
    asm("cvt.rna.tf32.f32 %0, %1;" : "=r"(u) : "f"(x));
    return u;
}

// m16n8k8 tf32 mma, row.col, fp32 accumulate (sm_80+ baseline ISA)
__device__ __forceinline__ void mma8(float* d, const uint32_t* a,
                                     uint32_t b0, uint32_t b1) {
    asm volatile(
        "mma.sync.aligned.m16n8k8.row.col.f32.tf32.tf32.f32 "
        "{%0,%1,%2,%3}, {%4,%5,%6,%7}, {%8,%9}, {%0,%1,%2,%3};"
        : "+f"(d[0]), "+f"(d[1]), "+f"(d[2]), "+f"(d[3])
        : "r"(a[0]), "r"(a[1]), "r"(a[2]), "r"(a[3]), "r"(b0), "r"(b1));
}

// ===========================================================================
// 32x32 tiled transpose: out[C,R] = in[R,C]^T  (dims multiples of 32)
// ===========================================================================
__global__ void transpose_kernel(const float* __restrict__ in,
                                 float* __restrict__ out, int R, int C) {
    __shared__ float t[32][33];
    const int bx = blockIdx.x * 32;
    const int by = blockIdx.y * 32;
    #pragma unroll
    for (int i = 0; i < 32; i += 8)
        t[threadIdx.y + i][threadIdx.x] =
            in[(size_t)(by + threadIdx.y + i) * C + bx + threadIdx.x];
    __syncthreads();
    #pragma unroll
    for (int i = 0; i < 32; i += 8)
        out[(size_t)(bx + threadIdx.y + i) * R + by + threadIdx.x] =
            t[threadIdx.x][threadIdx.y + i];
}

// ===========================================================================
// tf32 mma.sync GEMM: C[M,N] = A[M,K] @ Bt[N,K]^T (+bias)
// 128x128x32 CTA tile, 8 warps (2x4), each warp 64x32 (4x4 m16n8k8 tiles).
// smem stride 36 floats -> conflict-free fragment loads, double buffered.
// tf32 rounding (rna) applied at the smem-store path.
// ===========================================================================
#define GST 36
#define GSTAGE (2 * 128 * GST)               // uint32 per stage (A+B)
#define GEMM_SMEM_BYTES (2 * GSTAGE * 4)     // 73728

__global__ __launch_bounds__(256) void gemm_mma(
    const float* __restrict__ A, const float* __restrict__ Bt,
    const float* __restrict__ bias, float* __restrict__ C,
    int M, int N, int K)
{
    extern __shared__ uint32_t sm[];
    const int tid  = threadIdx.x;
    const int lane = tid & 31, wid = tid >> 5;
    const int gid  = lane >> 2, tig = lane & 3;
    const int warp_m = wid & 1, warp_n = wid >> 1;
    const int bm = blockIdx.y * 128;
    const int bn = blockIdx.x * 128;

    // loader mapping: each thread owns 4 float4 chunks per tile (rows +32 apart)
    const int lrow = tid >> 3;
    const int lch  = (tid & 7) << 2;        // float offset in k
    const float* Ap = A  + (size_t)(bm + lrow) * K + lch;
    const float* Bp = Bt + (size_t)(bn + lrow) * K + lch;
    const uint32_t sOff = (uint32_t)(lrow * GST + lch);

    float4 ra[4], rb[4];
    const int nkt = K / 32;

    // prologue: tile 0
    #pragma unroll
    for (int i = 0; i < 4; i++) {
        ra[i] = *(const float4*)(Ap + (size_t)(32 * i) * K);
        rb[i] = *(const float4*)(Bp + (size_t)(32 * i) * K);
    }
    #pragma unroll
    for (int i = 0; i < 4; i++) {
        uint4 va = { f2tf32(ra[i].x), f2tf32(ra[i].y), f2tf32(ra[i].z), f2tf32(ra[i].w) };
        uint4 vb = { f2tf32(rb[i].x), f2tf32(rb[i].y), f2tf32(rb[i].z), f2tf32(rb[i].w) };
        *(uint4*)&sm[sOff + i * 32 * GST]             = va;
        *(uint4*)&sm[128 * GST + sOff + i * 32 * GST] = vb;
    }
    __syncthreads();

    float acc[4][4][4] = {};

    for (int kt = 0; kt < nkt; kt++) {
        const int p = kt & 1;
        if (kt + 1 < nkt) {
            const int k0 = (kt + 1) * 32;
            #pragma unroll
            for (int i = 0; i < 4; i++) {
                ra[i] = *(const float4*)(Ap + (size_t)(32 * i) * K + k0);
                rb[i] = *(const float4*)(Bp + (size_t)(32 * i) * K + k0);
            }
        }

        const uint32_t* sA = sm + p * GSTAGE;
        const uint32_t* sB = sA + 128 * GST;
        #pragma unroll
        for (int ks = 0; ks < 4; ks++) {
            const int col = ks * 8 + tig;
            uint32_t af[4][4];
            #pragma unroll
            for (int im = 0; im < 4; im++) {
                const int base = (warp_m * 64 + im * 16 + gid) * GST + col;
                af[im][0] = sA[base];
                af[im][1] = sA[base + 8 * GST];
                af[im][2] = sA[base + 4];
                af[im][3] = sA[base + 8 * GST + 4];
            }
            uint32_t bf[4][2];
            #pragma unroll
            for (int jn = 0; jn < 4; jn++) {
                const int nb = (warp_n * 32 + jn * 8 + gid) * GST + col;
                bf[jn][0] = sB[nb];
                bf[jn][1] = sB[nb + 4];
            }
            #pragma unroll
            for (int im = 0; im < 4; im++)
                #pragma unroll
                for (int jn = 0; jn < 4; jn++)
                    mma8(acc[im][jn], af[im], bf[jn][0], bf[jn][1]);
        }

        if (kt + 1 < nkt) {
            uint32_t* dA = sm + (p ^ 1) * GSTAGE + sOff;
            uint32_t* dB = dA + 128 * GST;
            #pragma unroll
            for (int i = 0; i < 4; i++) {
                uint4 va = { f2tf32(ra[i].x), f2tf32(ra[i].y), f2tf32(ra[i].z), f2tf32(ra[i].w) };
                uint4 vb = { f2tf32(rb[i].x), f2tf32(rb[i].y), f2tf32(rb[i].z), f2tf32(rb[i].w) };
                *(uint4*)&dA[i * 32 * GST] = va;
                *(uint4*)&dB[i * 32 * GST] = vb;
            }
        }
        __syncthreads();
    }

    // epilogue
    #pragma unroll
    for (int im = 0; im < 4; im++) {
        const int row0 = bm + warp_m * 64 + im * 16 + gid;
        #pragma unroll
        for (int jn = 0; jn < 4; jn++) {
            const int col = bn + warp_n * 32 + jn * 8 + 2 * tig;
            float b0 = 0.f, b1 = 0.f;
            if (bias) { b0 = bias[col]; b1 = bias[col + 1]; }
            float2 v0 = { acc[im][jn][0] + b0, acc[im][jn][1] + b1 };
            float2 v1 = { acc[im][jn][2] + b0, acc[im][jn][3] + b1 };
            *(float2*)&C[(size_t)row0 * N + col]       = v0;
            *(float2*)&C[(size_t)(row0 + 8) * N + col] = v1;
        }
    }
}

// ===========================================================================
// tf32 mma.sync flash attention.
// 128 threads (4 warps). CTA = 64 Q rows of one (batch, head); warp = 16 rows.
// 64-key tiles, D=64. S via mma, fp32 online softmax, P -> tf32 -> smem
// (warp-private) -> PV via mma with fp32 accumulators.
// smem: Q,K,V,P each [64][68] floats = 69632 B.
// ===========================================================================
#define FST 68
#define FLASH_SMEM_BYTES (4 * 64 * FST * 4)

__global__ __launch_bounds__(128) void flash_mma(
    const float* __restrict__ Q, const float* __restrict__ KV,
    float* __restrict__ O)
{
    extern __shared__ uint32_t smf[];
    uint32_t* sQ = smf;
    uint32_t* sK = smf + 64 * FST;
    uint32_t* sV = smf + 2 * 64 * FST;
    uint32_t* sP = smf + 3 * 64 * FST;

    const int tid  = threadIdx.x;
    const int lane = tid & 31, wid = tid >> 5;
    const int gid  = lane >> 2, tig = lane & 3;
    const int wrow = wid * 16;
    const int q0   = blockIdx.x * 64;
    const int bh   = blockIdx.y;
    const int b    = bh >> 4;
    const int h    = bh & 15;

    const float* Qb = Q  + (size_t)b * NSEQ * NINNER     + (size_t)h * NDH;
    const float* Kb = KV + (size_t)b * NSEQ * 2 * NINNER + (size_t)h * NDH;
    const float* Vb = Kb + NINNER;
    float*       Ob = O  + (size_t)b * NSEQ * NINNER     + (size_t)h * NDH;

    // load Q tile (64x64), tf32-rounded
    #pragma unroll
    for (int i = 0; i < 8; i++) {
        const int fid = tid + 128 * i;
        const int row = fid >> 4;
        const int c4  = (fid & 15) << 2;
        float4 v = *(const float4*)&Qb[(size_t)(q0 + row) * NINNER + c4];
        uint4 u = { f2tf32(v.x), f2tf32(v.y), f2tf32(v.z), f2tf32(v.w) };
        *(uint4*)&sQ[row * FST + c4] = u;
    }

    float o[8][4] = {};
    float mr0 = -INFINITY, mr1 = -INFINITY, lr0 = 0.f, lr1 = 0.f;
    const float scale = 0.125f;   // 64^-0.5

    for (int j0 = 0; j0 < NSEQ; j0 += 64) {
        __syncthreads();   // prior iter's sK/sV reads complete
        #pragma unroll
        for (int i = 0; i < 8; i++) {
            const int fid = tid + 128 * i;
            const int row = fid >> 4;
            const int c4  = (fid & 15) << 2;
            const size_t g = (size_t)(j0 + row) * (2 * NINNER) + c4;
            float4 kv = *(const float4*)&Kb[g];
            uint4 u = { f2tf32(kv.x), f2tf32(kv.y), f2tf32(kv.z), f2tf32(kv.w) };
            *(uint4*)&sK[row * FST + c4] = u;
        }
        #pragma unroll
        for (int i = 0; i < 8; i++) {
            const int fid = tid + 128 * i;
            const int row = fid >> 4;
            const int c4  = (fid & 15) << 2;
            const size_t g = (size_t)(j0 + row) * (2 * NINNER) + c4;
            float4 vv = *(const float4*)&Vb[g];
            uint4 u = { f2tf32(vv.x), f2tf32(vv.y), f2tf32(vv.z), f2tf32(vv.w) };
            *(uint4*)&sV[row * FST + c4] = u;
        }
        __syncthreads();

        // S = Q @ K^T  (warp: 16 rows x 64 keys, 8 n-tiles)
        float s[8][4] = {};
        #pragma unroll
        for (int ks = 0; ks < 8; ks++) {
            const int col  = ks * 8 + tig;
            const int base = (wrow + gid) * FST + col;
            uint32_t qa[4];
            qa[0] = sQ[base];
            qa[1] = sQ[base + 8 * FST];
            qa[2] = sQ[base + 4];
            qa[3] = sQ[base + 8 * FST + 4];
            #pragma unroll
            for (int jn = 0; jn < 8; jn++) {
                const int kb = (jn * 8 + gid) * FST + col;
                mma8(s[jn], qa, sK[kb], sK[kb + 4]);
            }
        }

        // online softmax (rows gid -> c0,c1 ; gid+8 -> c2,c3)
        float mx0 = -INFINITY, mx1 = -INFINITY;
        #pragma unroll
        for (int jn = 0; jn < 8; jn++) {
            #pragma unroll
            for (int c = 0; c < 4; c++) s[jn][c] *= scale;
            mx0 = fmaxf(mx0, fmaxf(s[jn][0], s[jn][1]));
            mx1 = fmaxf(mx1, fmaxf(s[jn][2], s[jn][3]));
        }
        mx0 = fmaxf(mx0, __shfl_xor_sync(0xffffffffu, mx0, 1));
        mx0 = fmaxf(mx0, __shfl_xor_sync(0xffffffffu, mx0, 2));
        mx1 = fmaxf(mx1, __shfl_xor_sync(0xffffffffu, mx1, 1));
        mx1 = fmaxf(mx1, __shfl_xor_sync(0xffffffffu, mx1, 2));

        const float mn0 = fmaxf(mr0, mx0);
        const float mn1 = fmaxf(mr1, mx1);
        const float al0 = __expf(mr0 - mn0);
        const float al1 = __expf(mr1 - mn1);
        mr0 = mn0; mr1 = mn1;

        float rs0 = 0.f, rs1 = 0.f;
        #pragma unroll
        for (int jn = 0; jn < 8; jn++) {
            const float p0 = __expf(s[jn][0] - mn0);
            const float p1 = __expf(s[jn][1] - mn0);
            const float p2 = __expf(s[jn][2] - mn1);
            const float p3 = __expf(s[jn][3] - mn1);
            rs0 += p0 + p1;
            rs1 += p2 + p3;
            const int pb = (wrow + gid) * FST + jn * 8 + 2 * tig;
            sP[pb]               = f2tf32(p0);
            sP[pb + 1]           = f2tf32(p1);
            sP[pb + 8 * FST]     = f2tf32(p2);
            sP[pb + 8 * FST + 1] = f2tf32(p3);
        }
        rs0 += __shfl_xor_sync(0xffffffffu, rs0, 1);
        rs0 += __shfl_xor_sync(0xffffffffu, rs0, 2);
        rs1 += __shfl_xor_sync(0xffffffffu, rs1, 1);
        rs1 += __shfl_xor_sync(0xffffffffu, rs1, 2);
        lr0 = lr0 * al0 + rs0;
        lr1 = lr1 * al1 + rs1;

        #pragma unroll
        for (int dt = 0; dt < 8; dt++) {
            o[dt][0] *= al0; o[dt][1] *= al0;
            o[dt][2] *= al1; o[dt][3] *= al1;
        }
        __syncwarp();   // P visible within the warp

        // O += P @ V
        #pragma unroll
        for (int ks = 0; ks < 8; ks++) {
            const int col  = ks * 8 + tig;
            const int base = (wrow + gid) * FST + col;
            uint32_t pa[4];
            pa[0] = sP[base];
            pa[1] = sP[base + 8 * FST];
            pa[2] = sP[base + 4];
            pa[3] = sP[base + 8 * FST + 4];
            #pragma unroll
            for (int dt = 0; dt < 8; dt++) {
                const int vb = (ks * 8 + tig) * FST + dt * 8 + gid;
                mma8(o[dt], pa, sV[vb], sV[vb + 4 * FST]);
            }
        }
    }

    // epilogue
    const float inv0 = 1.0f / lr0;
    const float inv1 = 1.0f / lr1;
    const int r0 = q0 + wrow + gid;
    #pragma unroll
    for (int dt = 0; dt < 8; dt++) {
        const int col = dt * 8 + 2 * tig;
        float2 v0 = { o[dt][0] * inv0, o[dt][1] * inv0 };
        float2 v1 = { o[dt][2] * inv1, o[dt][3] * inv1 };
        *(float2*)&Ob[(size_t)r0 * NINNER + col]       = v0;
        *(float2*)&Ob[(size_t)(r0 + 8) * NINNER + col] = v1;
    }
}

// ===========================================================================
extern "C" void kernel_launch(void* const* d_in, const int* in_sizes, int n_in,
                              void* d_out, int out_size)
{
    const float* X   = (const float*)d_in[0];
    const float* Wq  = (const float*)d_in[1];
    const float* Wkv = (const float*)d_in[2];
    const float* Wo  = (const float*)d_in[3];
    const float* bo  = (const float*)d_in[4];
    float* out = (float*)d_out;

    float *Qb, *KVb, *Ab, *WqT, *WkvT, *WoT;
    cudaGetSymbolAddress((void**)&Qb,   g_Q);
    cudaGetSymbolAddress((void**)&KVb,  g_KV);
    cudaGetSymbolAddress((void**)&Ab,   g_A);
    cudaGetSymbolAddress((void**)&WqT,  g_WqT);
    cudaGetSymbolAddress((void**)&WkvT, g_WkvT);
    cudaGetSymbolAddress((void**)&WoT,  g_WoT);

    cudaFuncSetAttribute(gemm_mma, cudaFuncAttributeMaxDynamicSharedMemorySize,
                         GEMM_SMEM_BYTES);
    cudaFuncSetAttribute(flash_mma, cudaFuncAttributeMaxDynamicSharedMemorySize,
                         FLASH_SMEM_BYTES);

    dim3 tb(32, 8);
    transpose_kernel<<<dim3(NINNER / 32, DMODEL / 32), tb>>>(Wq,  WqT,  DMODEL, NINNER);
    transpose_kernel<<<dim3(2 * NINNER / 32, DMODEL / 32), tb>>>(Wkv, WkvT, DMODEL, 2 * NINNER);
    transpose_kernel<<<dim3(DMODEL / 32, NINNER / 32), tb>>>(Wo,  WoT,  NINNER, DMODEL);

    // Q = X @ Wq
    gemm_mma<<<dim3(NINNER / 128, MTOT / 128), 256, GEMM_SMEM_BYTES>>>(
        X, WqT, nullptr, Qb, MTOT, NINNER, DMODEL);
    // KV = X @ Wkv
    gemm_mma<<<dim3(2 * NINNER / 128, MTOT / 128), 256, GEMM_SMEM_BYTES>>>(
        X, WkvT, nullptr, KVb, MTOT, 2 * NINNER, DMODEL);
    // attention
    flash_mma<<<dim3(NSEQ / 64, NB * NH), 128, FLASH_SMEM_BYTES>>>(Qb, KVb, Ab);
    // out = A @ Wo + bo
    gemm_mma<<<dim3(DMODEL / 128, MTOT / 128), 256, GEMM_SMEM_BYTES>>>(
        Ab, WoT, bo, out, MTOT, DMODEL, NINNER);
}

// round 10
// speedup vs baseline: 5.2336x; 1.1908x over previous
#include <cuda_runtime.h>
#include <math.h>
#include <stdint.h>

// Problem shape (fixed per reference)
#define NB     2
#define NSEQ   2048
#define DMODEL 1024
#define NINNER 1024
#define NH     16
#define NDH    64
#define MTOT   (NB * NSEQ)   // 4096

// Scratch (allocation-free rule: __device__ globals)
__device__ float g_Q  [MTOT * NINNER];        // 16 MB
__device__ float g_KV [MTOT * 2 * NINNER];    // 32 MB
__device__ float g_A  [MTOT * NINNER];        // 16 MB
__device__ float g_WqT [NINNER * DMODEL];     // 4 MB   [N][K]
__device__ float g_WkvT[2 * NINNER * DMODEL]; // 8 MB   [N][K]
__device__ float g_WoT [DMODEL * NINNER];     // 4 MB   [N][K]

// ===========================================================================
// Helpers (baseline PTX only — ptxas targets sm_103, no 'a' features)
// ===========================================================================
__device__ __forceinline__ uint32_t f2tf32(float x) {
    uint32_t u;
    asm("cvt.rna.tf32.f32 %0, %1;" : "=r"(u) : "f"(x));
    return u;
}

// m16n8k8 tf32 mma, row.col, fp32 accumulate
__device__ __forceinline__ void mma8(float* d, const uint32_t* a,
                                     uint32_t b0, uint32_t b1) {
    asm volatile(
        "mma.sync.aligned.m16n8k8.row.col.f32.tf32.tf32.f32 "
        "{%0,%1,%2,%3}, {%4,%5,%6,%7}, {%8,%9}, {%0,%1,%2,%3};"
        : "+f"(d[0]), "+f"(d[1]), "+f"(d[2]), "+f"(d[3])
        : "r"(a[0]), "r"(a[1]), "r"(a[2]), "r"(a[3]), "r"(b0), "r"(b1));
}

// ===========================================================================
// 32x32 tiled transpose: out[C,R] = in[R,C]^T
// ===========================================================================
__global__ void transpose_kernel(const float* __restrict__ in,
                                 float* __restrict__ out, int R, int C) {
    __shared__ float t[32][33];
    const int bx = blockIdx.x * 32;
    const int by = blockIdx.y * 32;
    #pragma unroll
    for (int i = 0; i < 32; i += 8)
        t[threadIdx.y + i][threadIdx.x] =
            in[(size_t)(by + threadIdx.y + i) * C + bx + threadIdx.x];
    __syncthreads();
    #pragma unroll
    for (int i = 0; i < 32; i += 8)
        out[(size_t)(bx + threadIdx.y + i) * R + by + threadIdx.x] =
            t[threadIdx.x][threadIdx.y + i];
}

// ===========================================================================
// tf32 mma.sync GEMM: C[M,N] = A[M,K] @ Bt[N,K]^T (+bias)
// 128x128x32 CTA tile, 8 warps, double-buffered smem stride 36.
// ===========================================================================
#define GST 36
#define GSTAGE (2 * 128 * GST)
#define GEMM_SMEM_BYTES (2 * GSTAGE * 4)     // 73728

__global__ __launch_bounds__(256, 2) void gemm_mma(
    const float* __restrict__ A, const float* __restrict__ Bt,
    const float* __restrict__ bias, float* __restrict__ C,
    int M, int N, int K)
{
    extern __shared__ uint32_t sm[];
    const int tid  = threadIdx.x;
    const int lane = tid & 31, wid = tid >> 5;
    const int gid  = lane >> 2, tig = lane & 3;
    const int warp_m = wid & 1, warp_n = wid >> 1;
    const int bm = blockIdx.y * 128;
    const int bn = blockIdx.x * 128;

    const int lrow = tid >> 3;
    const int lch  = (tid & 7) << 2;
    const float* Ap = A  + (size_t)(bm + lrow) * K + lch;
    const float* Bp = Bt + (size_t)(bn + lrow) * K + lch;
    const uint32_t sOff = (uint32_t)(lrow * GST + lch);

    float4 ra[4], rb[4];
    const int nkt = K / 32;

    #pragma unroll
    for (int i = 0; i < 4; i++) {
        ra[i] = *(const float4*)(Ap + (size_t)(32 * i) * K);
        rb[i] = *(const float4*)(Bp + (size_t)(32 * i) * K);
    }
    #pragma unroll
    for (int i = 0; i < 4; i++) {
        uint4 va = { f2tf32(ra[i].x), f2tf32(ra[i].y), f2tf32(ra[i].z), f2tf32(ra[i].w) };
        uint4 vb = { f2tf32(rb[i].x), f2tf32(rb[i].y), f2tf32(rb[i].z), f2tf32(rb[i].w) };
        *(uint4*)&sm[sOff + i * 32 * GST]             = va;
        *(uint4*)&sm[128 * GST + sOff + i * 32 * GST] = vb;
    }
    __syncthreads();

    float acc[4][4][4] = {};

    for (int kt = 0; kt < nkt; kt++) {
        const int p = kt & 1;
        if (kt + 1 < nkt) {
            const int k0 = (kt + 1) * 32;
            #pragma unroll
            for (int i = 0; i < 4; i++) {
                ra[i] = *(const float4*)(Ap + (size_t)(32 * i) * K + k0);
                rb[i] = *(const float4*)(Bp + (size_t)(32 * i) * K + k0);
            }
        }

        const uint32_t* sA = sm + p * GSTAGE;
        const uint32_t* sB = sA + 128 * GST;
        #pragma unroll
        for (int ks = 0; ks < 4; ks++) {
            const int col = ks * 8 + tig;
            uint32_t af[4][4];
            #pragma unroll
            for (int im = 0; im < 4; im++) {
                const int base = (warp_m * 64 + im * 16 + gid) * GST + col;
                af[im][0] = sA[base];
                af[im][1] = sA[base + 8 * GST];
                af[im][2] = sA[base + 4];
                af[im][3] = sA[base + 8 * GST + 4];
            }
            uint32_t bf[4][2];
            #pragma unroll
            for (int jn = 0; jn < 4; jn++) {
                const int nb = (warp_n * 32 + jn * 8 + gid) * GST + col;
                bf[jn][0] = sB[nb];
                bf[jn][1] = sB[nb + 4];
            }
            #pragma unroll
            for (int im = 0; im < 4; im++)
                #pragma unroll
                for (int jn = 0; jn < 4; jn++)
                    mma8(acc[im][jn], af[im], bf[jn][0], bf[jn][1]);
        }

        if (kt + 1 < nkt) {
            uint32_t* dA = sm + (p ^ 1) * GSTAGE + sOff;
            uint32_t* dB = dA + 128 * GST;
            #pragma unroll
            for (int i = 0; i < 4; i++) {
                uint4 va = { f2tf32(ra[i].x), f2tf32(ra[i].y), f2tf32(ra[i].z), f2tf32(ra[i].w) };
                uint4 vb = { f2tf32(rb[i].x), f2tf32(rb[i].y), f2tf32(rb[i].z), f2tf32(rb[i].w) };
                *(uint4*)&dA[i * 32 * GST] = va;
                *(uint4*)&dB[i * 32 * GST] = vb;
            }
        }
        __syncthreads();
    }

    #pragma unroll
    for (int im = 0; im < 4; im++) {
        const int row0 = bm + warp_m * 64 + im * 16 + gid;
        #pragma unroll
        for (int jn = 0; jn < 4; jn++) {
            const int col = bn + warp_n * 32 + jn * 8 + 2 * tig;
            float b0 = 0.f, b1 = 0.f;
            if (bias) { b0 = bias[col]; b1 = bias[col + 1]; }
            float2 v0 = { acc[im][jn][0] + b0, acc[im][jn][1] + b1 };
            float2 v1 = { acc[im][jn][2] + b0, acc[im][jn][3] + b1 };
            *(float2*)&C[(size_t)row0 * N + col]       = v0;
            *(float2*)&C[(size_t)(row0 + 8) * N + col] = v1;
        }
    }
}

// ===========================================================================
// tf32 mma.sync flash attention (R7 math, R9 structure).
// 256 threads (8 warps), CTA = 128 Q rows of one (b,h); warp = 16 rows.
// 64-key tiles, D=64. Q frags hoisted (32 regs), scale folded into Q.
// P -> tf32 into retired sQ region (warp-private rows). V stride 72:
// PV B-frag bank = 8*tig+gid, conflict-free (R7 had a 2-way conflict).
// smem: sQ/sP 128*68 + sK 64*68 + sV 64*72 = 17664 words = 70656 B.
// launch_bounds(256,2): 2 CTAs/SM -> 16 warps/SM (R7 flash: 4 warps/SM).
// ===========================================================================
#define FST 68
#define VST 72
#define FQP  (128 * FST)
#define FKO  (64 * FST)
#define FLASH_SMEM_BYTES ((FQP + FKO + 64 * VST) * 4)   // 70656

__global__ __launch_bounds__(256, 2) void flash_mma(
    const float* __restrict__ Q, const float* __restrict__ KV,
    float* __restrict__ O)
{
    extern __shared__ uint32_t smf[];
    uint32_t* sQ = smf;              // becomes sP after Q frags hoisted
    uint32_t* sK = smf + FQP;
    uint32_t* sV = smf + FQP + FKO;

    const int tid  = threadIdx.x;
    const int lane = tid & 31, wid = tid >> 5;
    const int gid  = lane >> 2, tig = lane & 3;
    const int wrow = wid * 16;
    const int q0   = blockIdx.x * 128;
    const int bh   = blockIdx.y;
    const int b    = bh >> 4;
    const int h    = bh & 15;

    const float* Qb = Q  + (size_t)b * NSEQ * NINNER     + (size_t)h * NDH;
    const float* Kb = KV + (size_t)b * NSEQ * 2 * NINNER + (size_t)h * NDH;
    const float* Vb = Kb + NINNER;
    float*       Ob = O  + (size_t)b * NSEQ * NINNER     + (size_t)h * NDH;

    // load Q tile (128x64) -> tf32 smem, scale folded
    #pragma unroll
    for (int i = 0; i < 8; i++) {
        const int fid = tid + 256 * i;
        const int row = fid >> 4;
        const int c4  = (fid & 15) << 2;
        float4 v = *(const float4*)&Qb[(size_t)(q0 + row) * NINNER + c4];
        uint4 u = { f2tf32(v.x * 0.125f), f2tf32(v.y * 0.125f),
                    f2tf32(v.z * 0.125f), f2tf32(v.w * 0.125f) };
        *(uint4*)&sQ[row * FST + c4] = u;
    }
    __syncthreads();

    // hoist Q fragments for all 8 k-steps (warp's own 16 rows)
    uint32_t qf[8][4];
    {
        const int base = (wrow + gid) * FST;
        #pragma unroll
        for (int ks = 0; ks < 8; ks++) {
            const int w = ks * 8 + tig;
            qf[ks][0] = sQ[base + w];
            qf[ks][1] = sQ[base + 8 * FST + w];
            qf[ks][2] = sQ[base + w + 4];
            qf[ks][3] = sQ[base + 8 * FST + w + 4];
        }
    }

    float o[8][4] = {};
    float mr0 = -INFINITY, mr1 = -INFINITY, lr0 = 0.f, lr1 = 0.f;

    for (int j0 = 0; j0 < NSEQ; j0 += 64) {
        __syncthreads();   // prior iter's sK/sV reads done (also fences hoist)
        // K tile -> sK [key][d], stride 68
        #pragma unroll
        for (int i = 0; i < 4; i++) {
            const int fid = tid + 256 * i;
            const int row = fid >> 4;
            const int c4  = (fid & 15) << 2;
            float4 kv = *(const float4*)&Kb[(size_t)(j0 + row) * (2 * NINNER) + c4];
            uint4 u = { f2tf32(kv.x), f2tf32(kv.y), f2tf32(kv.z), f2tf32(kv.w) };
            *(uint4*)&sK[row * FST + c4] = u;
        }
        // V tile -> sV [key][d], stride 72
        #pragma unroll
        for (int i = 0; i < 4; i++) {
            const int fid = tid + 256 * i;
            const int row = fid >> 4;
            const int c4  = (fid & 15) << 2;
            float4 vv = *(const float4*)&Vb[(size_t)(j0 + row) * (2 * NINNER) + c4];
            uint4 u = { f2tf32(vv.x), f2tf32(vv.y), f2tf32(vv.z), f2tf32(vv.w) };
            *(uint4*)&sV[row * VST + c4] = u;
        }
        __syncthreads();

        // S = Q @ K^T  (16 rows x 64 keys per warp)
        float s[8][4] = {};
        #pragma unroll
        for (int ks = 0; ks < 8; ks++) {
            #pragma unroll
            for (int jn = 0; jn < 8; jn++) {
                const int kb = (jn * 8 + gid) * FST + ks * 8 + tig;
                mma8(s[jn], qf[ks], sK[kb], sK[kb + 4]);
            }
        }

        // online softmax (rows gid -> c0,c1 ; gid+8 -> c2,c3)
        float mx0 = -INFINITY, mx1 = -INFINITY;
        #pragma unroll
        for (int jn = 0; jn < 8; jn++) {
            mx0 = fmaxf(mx0, fmaxf(s[jn][0], s[jn][1]));
            mx1 = fmaxf(mx1, fmaxf(s[jn][2], s[jn][3]));
        }
        mx0 = fmaxf(mx0, __shfl_xor_sync(0xffffffffu, mx0, 1));
        mx0 = fmaxf(mx0, __shfl_xor_sync(0xffffffffu, mx0, 2));
        mx1 = fmaxf(mx1, __shfl_xor_sync(0xffffffffu, mx1, 1));
        mx1 = fmaxf(mx1, __shfl_xor_sync(0xffffffffu, mx1, 2));

        const float mn0 = fmaxf(mr0, mx0);
        const float mn1 = fmaxf(mr1, mx1);
        const float al0 = __expf(mr0 - mn0);
        const float al1 = __expf(mr1 - mn1);
        mr0 = mn0; mr1 = mn1;

        float rs0 = 0.f, rs1 = 0.f;
        {
            const int pb0 = (wrow + gid) * FST + 2 * tig;
            #pragma unroll
            for (int jn = 0; jn < 8; jn++) {
                const float p0 = __expf(s[jn][0] - mn0);
                const float p1 = __expf(s[jn][1] - mn0);
                const float p2 = __expf(s[jn][2] - mn1);
                const float p3 = __expf(s[jn][3] - mn1);
                rs0 += p0 + p1;
                rs1 += p2 + p3;
                sQ[pb0 + jn * 8]               = f2tf32(p0);   // sP overlays sQ
                sQ[pb0 + jn * 8 + 1]           = f2tf32(p1);
                sQ[pb0 + 8 * FST + jn * 8]     = f2tf32(p2);
                sQ[pb0 + 8 * FST + jn * 8 + 1] = f2tf32(p3);
            }
        }
        rs0 += __shfl_xor_sync(0xffffffffu, rs0, 1);
        rs0 += __shfl_xor_sync(0xffffffffu, rs0, 2);
        rs1 += __shfl_xor_sync(0xffffffffu, rs1, 1);
        rs1 += __shfl_xor_sync(0xffffffffu, rs1, 2);
        lr0 = lr0 * al0 + rs0;
        lr1 = lr1 * al1 + rs1;

        #pragma unroll
        for (int dt = 0; dt < 8; dt++) {
            o[dt][0] *= al0; o[dt][1] *= al0;
            o[dt][2] *= al1; o[dt][3] *= al1;
        }
        __syncwarp();   // P rows are warp-private

        // O += P @ V
        #pragma unroll
        for (int ks = 0; ks < 8; ks++) {
            uint32_t pa[4];
            const int base = (wrow + gid) * FST + ks * 8 + tig;
            pa[0] = sQ[base];
            pa[1] = sQ[base + 8 * FST];
            pa[2] = sQ[base + 4];
            pa[3] = sQ[base + 8 * FST + 4];
            #pragma unroll
            for (int dt = 0; dt < 8; dt++) {
                const int vb = (ks * 8 + tig) * VST + dt * 8 + gid;
                mma8(o[dt], pa, sV[vb], sV[vb + 4 * VST]);
            }
        }
    }

    // epilogue
    const float inv0 = 1.0f / lr0;
    const float inv1 = 1.0f / lr1;
    const int r0 = q0 + wrow + gid;
    #pragma unroll
    for (int dt = 0; dt < 8; dt++) {
        const int col = dt * 8 + 2 * tig;
        float2 v0 = { o[dt][0] * inv0, o[dt][1] * inv0 };
        float2 v1 = { o[dt][2] * inv1, o[dt][3] * inv1 };
        *(float2*)&Ob[(size_t)r0 * NINNER + col]       = v0;
        *(float2*)&Ob[(size_t)(r0 + 8) * NINNER + col] = v1;
    }
}

// ===========================================================================
extern "C" void kernel_launch(void* const* d_in, const int* in_sizes, int n_in,
                              void* d_out, int out_size)
{
    const float* X   = (const float*)d_in[0];
    const float* Wq  = (const float*)d_in[1];
    const float* Wkv = (const float*)d_in[2];
    const float* Wo  = (const float*)d_in[3];
    const float* bo  = (const float*)d_in[4];
    float* out = (float*)d_out;

    float *Qb, *KVb, *Ab, *WqT, *WkvT, *WoT;
    cudaGetSymbolAddress((void**)&Qb,   g_Q);
    cudaGetSymbolAddress((void**)&KVb,  g_KV);
    cudaGetSymbolAddress((void**)&Ab,   g_A);
    cudaGetSymbolAddress((void**)&WqT,  g_WqT);
    cudaGetSymbolAddress((void**)&WkvT, g_WkvT);
    cudaGetSymbolAddress((void**)&WoT,  g_WoT);

    cudaFuncSetAttribute(gemm_mma, cudaFuncAttributeMaxDynamicSharedMemorySize,
                         GEMM_SMEM_BYTES);
    cudaFuncSetAttribute(flash_mma, cudaFuncAttributeMaxDynamicSharedMemorySize,
                         FLASH_SMEM_BYTES);

    dim3 tb(32, 8);
    transpose_kernel<<<dim3(NINNER / 32, DMODEL / 32), tb>>>(Wq,  WqT,  DMODEL, NINNER);
    transpose_kernel<<<dim3(2 * NINNER / 32, DMODEL / 32), tb>>>(Wkv, WkvT, DMODEL, 2 * NINNER);
    transpose_kernel<<<dim3(DMODEL / 32, NINNER / 32), tb>>>(Wo,  WoT,  NINNER, DMODEL);

    // Q = X @ Wq
    gemm_mma<<<dim3(NINNER / 128, MTOT / 128), 256, GEMM_SMEM_BYTES>>>(
        X, WqT, nullptr, Qb, MTOT, NINNER, DMODEL);
    // KV = X @ Wkv
    gemm_mma<<<dim3(2 * NINNER / 128, MTOT / 128), 256, GEMM_SMEM_BYTES>>>(
        X, WkvT, nullptr, KVb, MTOT, 2 * NINNER, DMODEL);
    // attention
    flash_mma<<<dim3(NSEQ / 128, NB * NH), 256, FLASH_SMEM_BYTES>>>(Qb, KVb, Ab);
    // out = A @ Wo + bo
    gemm_mma<<<dim3(DMODEL / 128, MTOT / 128), 256, GEMM_SMEM_BYTES>>>(
        Ab, WoT, bo, out, MTOT, DMODEL, NINNER);
}